// round 2
// baseline (speedup 1.0000x reference)
#include <cuda_runtime.h>
#include <cuda_bf16.h>

#define THREADS 512
#define ITEMS   4
#define CHUNK   (THREADS * ITEMS)
#define NWARPS  (THREADS / 32)

__global__ __launch_bounds__(THREADS, 2)
void traj_scan_kernel(const int*   __restrict__ states,
                      const float* __restrict__ e0s,
                      const float* __restrict__ speed0,
                      const float* __restrict__ speed1,
                      const float* __restrict__ x0,
                      float*       __restrict__ X,
                      int T)
{
    const int b = blockIdx.x;
    const int*   srow = states + (size_t)b * T;
    const float* erow = e0s    + (size_t)b * (T + 1) * 3;
    float*       xrow = X      + (size_t)b * T * 3;

    const float sp0 = speed0[b];
    const float sp1 = speed1[b];
    const float ox = x0[3 * b + 0];
    const float oy = x0[3 * b + 1];
    const float oz = x0[3 * b + 2];
    const float DT = 0.1f;

    __shared__ int   s_wi[NWARPS];
    __shared__ float s_wx[NWARPS], s_wy[NWARPS], s_wz[NWARPS];

    int   carry_k = 0;
    float carry_x = 0.f, carry_y = 0.f, carry_z = 0.f;

    const int lane = threadIdx.x & 31;
    const int wid  = threadIdx.x >> 5;

    for (int base = 0; base < T; base += CHUNK) {
        const int t0 = base + threadIdx.x * ITEMS;

        // ---- load 4 states (vectorized when fully in-bounds) ----
        int st[ITEMS];
        if (t0 + ITEMS <= T) {
            int4 v = *reinterpret_cast<const int4*>(srow + t0);
            st[0] = v.x; st[1] = v.y; st[2] = v.z; st[3] = v.w;
        } else {
            #pragma unroll
            for (int i = 0; i < ITEMS; i++)
                st[i] = (t0 + i < T) ? srow[t0 + i] : 0;
        }

        // ---- thread-local inclusive tumble count ----
        int c[ITEMS];
        int run = 0;
        #pragma unroll
        for (int i = 0; i < ITEMS; i++) { run += (st[i] == 2); c[i] = run; }

        // ---- block inclusive scan of per-thread tumble sums ----
        int xs = run;
        #pragma unroll
        for (int d = 1; d < 32; d <<= 1) {
            int y = __shfl_up_sync(0xffffffffu, xs, d);
            if (lane >= d) xs += y;
        }
        if (lane == 31) s_wi[wid] = xs;
        __syncthreads();
        if (wid == 0) {
            int w = (lane < NWARPS) ? s_wi[lane] : 0;
            #pragma unroll
            for (int d = 1; d < 32; d <<= 1) {
                int y = __shfl_up_sync(0xffffffffu, w, d);
                if (lane >= d) w += y;
            }
            if (lane < NWARPS) s_wi[lane] = w;
        }
        __syncthreads();
        const int thr_excl      = (wid ? s_wi[wid - 1] : 0) + (xs - run);
        const int chunk_tumbles = s_wi[NWARPS - 1];
        const int kbase         = carry_k + thr_excl;

        // ---- gather e0s and build velocities; local inclusive float3 scan ----
        float vx[ITEMS], vy[ITEMS], vz[ITEMS];
        float ax = 0.f, ay = 0.f, az = 0.f;
        #pragma unroll
        for (int i = 0; i < ITEMS; i++) {
            const int t = t0 + i;
            if (t < T && st[i] != 2) {
                const int k = kbase + c[i];
                const float* e = erow + (size_t)k * 3;
                const float sp = (st[i] == 0) ? sp0 : sp1;
                ax = fmaf(__ldg(e + 0), sp, ax);
                ay = fmaf(__ldg(e + 1), sp, ay);
                az = fmaf(__ldg(e + 2), sp, az);
            }
            vx[i] = ax; vy[i] = ay; vz[i] = az;
        }

        // ---- block inclusive scan of per-thread float3 sums ----
        float sx = ax, sy = ay, sz = az;
        #pragma unroll
        for (int d = 1; d < 32; d <<= 1) {
            float tx = __shfl_up_sync(0xffffffffu, sx, d);
            float ty = __shfl_up_sync(0xffffffffu, sy, d);
            float tz = __shfl_up_sync(0xffffffffu, sz, d);
            if (lane >= d) { sx += tx; sy += ty; sz += tz; }
        }
        if (lane == 31) { s_wx[wid] = sx; s_wy[wid] = sy; s_wz[wid] = sz; }
        __syncthreads();
        if (wid == 0) {
            float wx = (lane < NWARPS) ? s_wx[lane] : 0.f;
            float wy = (lane < NWARPS) ? s_wy[lane] : 0.f;
            float wz = (lane < NWARPS) ? s_wz[lane] : 0.f;
            #pragma unroll
            for (int d = 1; d < 32; d <<= 1) {
                float tx = __shfl_up_sync(0xffffffffu, wx, d);
                float ty = __shfl_up_sync(0xffffffffu, wy, d);
                float tz = __shfl_up_sync(0xffffffffu, wz, d);
                if (lane >= d) { wx += tx; wy += ty; wz += tz; }
            }
            if (lane < NWARPS) { s_wx[lane] = wx; s_wy[lane] = wy; s_wz[lane] = wz; }
        }
        __syncthreads();
        float ex = carry_x + (sx - ax);
        float ey = carry_y + (sy - ay);
        float ez = carry_z + (sz - az);
        if (wid) { ex += s_wx[wid - 1]; ey += s_wy[wid - 1]; ez += s_wz[wid - 1]; }
        const float totx = s_wx[NWARPS - 1];
        const float toty = s_wy[NWARPS - 1];
        const float totz = s_wz[NWARPS - 1];

        // ---- write output: 12 contiguous floats per thread (3x float4) ----
        if (t0 + ITEMS <= T) {
            float o[12];
            #pragma unroll
            for (int i = 0; i < ITEMS; i++) {
                o[3 * i + 0] = ox + DT * (ex + vx[i]);
                o[3 * i + 1] = oy + DT * (ey + vy[i]);
                o[3 * i + 2] = oz + DT * (ez + vz[i]);
            }
            float4* p = reinterpret_cast<float4*>(xrow + (size_t)t0 * 3);
            p[0] = make_float4(o[0], o[1], o[2],  o[3]);
            p[1] = make_float4(o[4], o[5], o[6],  o[7]);
            p[2] = make_float4(o[8], o[9], o[10], o[11]);
        } else {
            #pragma unroll
            for (int i = 0; i < ITEMS; i++) {
                const int t = t0 + i;
                if (t < T) {
                    float* o = xrow + (size_t)t * 3;
                    o[0] = ox + DT * (ex + vx[i]);
                    o[1] = oy + DT * (ey + vy[i]);
                    o[2] = oz + DT * (ez + vz[i]);
                }
            }
        }

        carry_k += chunk_tumbles;
        carry_x += totx; carry_y += toty; carry_z += totz;
        __syncthreads();  // protect smem reuse next iteration
    }
}

extern "C" void kernel_launch(void* const* d_in, const int* in_sizes, int n_in,
                              void* d_out, int out_size)
{
    const int*   states = (const int*)  d_in[0];
    const float* e0s    = (const float*)d_in[1];
    const float* sp0    = (const float*)d_in[2];
    const float* sp1    = (const float*)d_in[3];
    const float* x0     = (const float*)d_in[4];
    float*       X      = (float*)d_out;

    const int B = in_sizes[2];           // speed_0 has B elements
    const int T = in_sizes[0] / B;       // states is (B, T)

    traj_scan_kernel<<<B, THREADS>>>(states, e0s, sp0, sp1, x0, X, T);
}